// round 11
// baseline (speedup 1.0000x reference)
#include <cuda_runtime.h>
#include <cuda_bf16.h>

#define NB     16
#define ENC_T  512
#define DEC_T  1024
#define NDIM   512
#define NSUB   18
#define NCTAS  (NB * NSUB)   // 288
#define NTHR   256
#define PADZ   16
#define PADTOT 544
#define ALPHA  2.885390082f  // 2*log2(e)

typedef unsigned long long u64;

// smem layout (bytes per CTA), 16B-aligned (max nd = 30)
#define OFF_W    0            // 30*32*16 = 15360
#define OFF_CC   15360        // 30*512*4 = 61440
#define OFF_RED  76800        // 4*512*4  = 8192 (aliased by float2 GEMV partials)
#define OFF_SPAD 84992        // 544*4    = 2176
#define OFF_Q    87168        // 128
#define OFF_WL   87296        // 128
#define OFF_WRED 87424        // 64
#define SM_BYTES 87488

__device__ __forceinline__ u64 pack2(float x, float y) {
    u64 r;
    asm("mov.b64 %0, {%1, %2};" : "=l"(r)
        : "r"(__float_as_uint(x)), "r"(__float_as_uint(y)));
    return r;
}
__device__ __forceinline__ void unpack2(u64 v, float& x, float& y) {
    unsigned a, b;
    asm("mov.b64 {%0, %1}, %2;" : "=r"(a), "=r"(b) : "l"(v));
    x = __uint_as_float(a); y = __uint_as_float(b);
}
__device__ __forceinline__ u64 ffma2(u64 a, u64 b, u64 c) {
    u64 d;
    asm("fma.rn.f32x2 %0, %1, %2, %3;" : "=l"(d) : "l"(a), "l"(b), "l"(c));
    return d;
}
__device__ __forceinline__ float hsum2(u64 v) {
    float x, y; unpack2(v, x, y); return x + y;
}
// input X is already ALPHA-scaled: tanh = 1 - 2/(ex2(X)+1)
__device__ __forceinline__ float tanh_pre(float X) {
    float e;
    asm("ex2.approx.f32 %0, %1;" : "=f"(e) : "f"(X));
    float r;
    asm("rcp.approx.f32 %0, %1;" : "=f"(r) : "f"(e + 1.0f));
    return fmaf(-2.0f, r, 1.0f);
}

// ---------- persistent globals ----------
__device__ float    g_lpart[2][NB][NSUB][ENC_T];   // [sub][t]: coalesced R/W
__device__ unsigned g_bar[NB][32];                 // 128B padding per batch

__global__ void attn_init() {
    if (threadIdx.x < NB) g_bar[threadIdx.x][0] = 0;
}

__global__ void __launch_bounds__(NTHR, 2)
attn_persist(const float* __restrict__ enc,
             const float* __restrict__ mel,
             const int*   __restrict__ out_len,
             const float* __restrict__ w_lin,
             const float* __restrict__ w_conv,
             float* __restrict__ att_out,
             float* __restrict__ att_sc) {
    extern __shared__ char smraw[];
    ulonglong2* w2   = (ulonglong2*)(smraw + OFF_W);
    float*      cc_s = (float*)(smraw + OFF_CC);
    float*      red  = (float*)(smraw + OFF_RED);
    float2*     red2 = (float2*)(smraw + OFF_RED);
    float*      spad = (float*)(smraw + OFF_SPAD);
    float*      q_s  = (float*)(smraw + OFF_Q);
    float*      wl_s = (float*)(smraw + OFF_WL);
    float*      wred = (float*)(smraw + OFF_WRED);

    const int tid  = threadIdx.x;
    const int b    = blockIdx.x & 15;     // batch (adjacent bids -> different batches)
    const int sub  = blockIdx.x >> 4;     // 0..17 d-slice
    const int nd   = (sub < 4) ? 30 : 28;                           // even sizes
    const int d0   = (sub < 4) ? 30 * sub : 120 + 28 * (sub - 4);   // even d0
    const int nd2  = nd >> 1;
    const int warp = tid >> 5, lane = tid & 31;
    const int dg   = warp >> 1;                       // 0..3 d-group
    const int tslot = ((warp & 1) << 5) | lane;       // 0..63
    const int t0   = tslot << 3;                      // 8 t per thread
    const int ol   = out_len[b];

    // weights (pre-scaled by ALPHA): per local d, 16 pairs for w0 then 16 for w1
    for (int e = tid; e < nd * 32; e += NTHR) {
        int d = e >> 5, j = e & 31, i = j & 15;
        const float* wb = w_conv + (size_t)(d0 + d) * 62 + ((j < 16) ? 0 : 31);
        float wm1 = (i > 0)  ? wb[2*i - 1] * ALPHA : 0.0f;
        float w0v = wb[2*i] * ALPHA;
        float wp1 = (i < 15) ? wb[2*i + 1] * ALPHA : 0.0f;
        ulonglong2 v;
        v.x = pack2(wm1, w0v);
        v.y = pack2(w0v, wp1);
        w2[(d << 5) + j] = v;
    }
    if (tid < nd) {
        wl_s[tid] = w_lin[d0 + tid];
        q_s[tid]  = (0 < ol) ? mel[(size_t)(b * DEC_T) * NDIM + d0 + tid] * ALPHA : 0.0f;
    }
    for (int i = tid; i < PADTOT; i += NTHR) spad[i] = 0.0f;
    for (int i = tid; i < nd * 512; i += NTHR) cc_s[i] = 0.0f;
    __syncthreads();

    unsigned bar_target = 0;

    for (int s = 0; s < DEC_T; ++s) {
        const int par = s & 1;

        // ===== phase A: conv0(score) + incremental conv1(cum), ALPHA-scaled =====
        u64 Ws[20];
        {
            const float4* sp4 = reinterpret_cast<const float4*>(spad + t0);
#pragma unroll
            for (int j = 0; j < 10; ++j) {
                float4 f = sp4[j];
                Ws[2*j]   = pack2(f.x, f.y);
                Ws[2*j+1] = pack2(f.z, f.w);
            }
        }

        float lacc0=0.f,lacc1=0.f,lacc2=0.f,lacc3=0.f;
        float lacc4=0.f,lacc5=0.f,lacc6=0.f,lacc7=0.f;

#pragma unroll 1
        for (int d = dg; d < nd; d += 4) {
            float* ccp = cc_s + (d << 9) + t0;
            float4 cc0 = reinterpret_cast<float4*>(ccp)[0];
            float4 cc1 = reinterpret_cast<float4*>(ccp)[1];
            const ulonglong2* wr = w2 + (d << 5);
            const float qd = q_s[d], wld = wl_s[d];
            const u64 qi = pack2(qd, 0.0f);

            u64 as0=qi,as1=qi,as2=qi,as3=qi,as4=qi,as5=qi,as6=qi,as7=qi;
            u64 av0=pack2(cc0.x,0.f), av1=pack2(cc0.y,0.f),
                av2=pack2(cc0.z,0.f), av3=pack2(cc0.w,0.f),
                av4=pack2(cc1.x,0.f), av5=pack2(cc1.y,0.f),
                av6=pack2(cc1.z,0.f), av7=pack2(cc1.w,0.f);
#pragma unroll
            for (int i = 0; i < 16; ++i) {
                ulonglong2 A  = wr[i];
                ulonglong2 Bv = wr[16 + i];
                as0 = ffma2(A.x,  Ws[i],     as0);
                as1 = ffma2(A.y,  Ws[i + 1], as1);
                as2 = ffma2(A.x,  Ws[i + 1], as2);
                as3 = ffma2(A.y,  Ws[i + 2], as3);
                as4 = ffma2(A.x,  Ws[i + 2], as4);
                as5 = ffma2(A.y,  Ws[i + 3], as5);
                as6 = ffma2(A.x,  Ws[i + 3], as6);
                as7 = ffma2(A.y,  Ws[i + 4], as7);
                av0 = ffma2(Bv.x, Ws[i],     av0);
                av1 = ffma2(Bv.y, Ws[i + 1], av1);
                av2 = ffma2(Bv.x, Ws[i + 1], av2);
                av3 = ffma2(Bv.y, Ws[i + 2], av3);
                av4 = ffma2(Bv.x, Ws[i + 2], av4);
                av5 = ffma2(Bv.y, Ws[i + 3], av5);
                av6 = ffma2(Bv.x, Ws[i + 3], av6);
                av7 = ffma2(Bv.y, Ws[i + 4], av7);
            }
            // c_i = cc + alpha*conv1(score)  (cc folded into av init)
            float c0 = hsum2(av0), c1 = hsum2(av1), c2 = hsum2(av2), c3 = hsum2(av3);
            float c4 = hsum2(av4), c5 = hsum2(av5), c6 = hsum2(av6), c7 = hsum2(av7);
            reinterpret_cast<float4*>(ccp)[0] = make_float4(c0, c1, c2, c3);
            reinterpret_cast<float4*>(ccp)[1] = make_float4(c4, c5, c6, c7);

            lacc0 = fmaf(wld, tanh_pre(hsum2(as0) + c0), lacc0);
            lacc1 = fmaf(wld, tanh_pre(hsum2(as1) + c1), lacc1);
            lacc2 = fmaf(wld, tanh_pre(hsum2(as2) + c2), lacc2);
            lacc3 = fmaf(wld, tanh_pre(hsum2(as3) + c3), lacc3);
            lacc4 = fmaf(wld, tanh_pre(hsum2(as4) + c4), lacc4);
            lacc5 = fmaf(wld, tanh_pre(hsum2(as5) + c5), lacc5);
            lacc6 = fmaf(wld, tanh_pre(hsum2(as6) + c6), lacc6);
            lacc7 = fmaf(wld, tanh_pre(hsum2(as7) + c7), lacc7);
        }
        {
            float* rp = red + (dg << 9) + t0;
            reinterpret_cast<float4*>(rp)[0] = make_float4(lacc0, lacc1, lacc2, lacc3);
            reinterpret_cast<float4*>(rp)[1] = make_float4(lacc4, lacc5, lacc6, lacc7);
        }
        __syncthreads();
#pragma unroll
        for (int k = 0; k < 2; ++k) {
            const int t = tid + (k << 8);
            float lp = red[t] + red[512 + t] + red[1024 + t] + red[1536 + t];
            __stcg(&g_lpart[par][b][sub][t], lp);
        }

        // ===== per-batch barrier (release arrive, acquire poll; padded line) =====
        __syncthreads();
        if (tid == 0) {
            bar_target += (unsigned)NSUB;
            asm volatile("red.release.gpu.global.add.u32 [%0], %1;"
                         :: "l"(&g_bar[b][0]), "r"(1u) : "memory");
            unsigned cur;
            for (;;) {
                asm volatile("ld.acquire.gpu.u32 %0, [%1];"
                             : "=r"(cur) : "l"(&g_bar[b][0]));
                if ((int)(cur - bar_target) >= 0) break;
                __nanosleep(32);
            }
        }
        __syncthreads();

        // ===== phase B: softmax (no max pass; |logit| <= ~18), ctx, q =====
        float lv0 = 0.0f, lv1 = 0.0f;
#pragma unroll
        for (int j = 0; j < NSUB; ++j) {
            lv0 += __ldcg(&g_lpart[par][b][j][tid]);
            lv1 += __ldcg(&g_lpart[par][b][j][tid + 256]);
        }
        const float e0 = __expf(lv0);
        const float e1 = __expf(lv1);
        float ssum = e0 + e1;
#pragma unroll
        for (int o = 16; o; o >>= 1) ssum += __shfl_xor_sync(0xffffffffu, ssum, o);
        if (lane == 0) wred[warp] = ssum;
        __syncthreads();
        if (warp == 0) {
            float v = (lane < 8) ? wred[lane] : 0.0f;
#pragma unroll
            for (int o = 4; o; o >>= 1) v += __shfl_xor_sync(0xffffffffu, v, o);
            if (lane == 0) wred[8] = __fdividef(1.0f, v);
        }
        __syncthreads();
        const float inv = wred[8];
        const float sc0 = e0 * inv, sc1 = e1 * inv;
        spad[PADZ + tid]       = sc0;
        spad[PADZ + tid + 256] = sc1;
        __syncthreads();

        // ctx[b, d-slice] = sum_t score[t] * enc[b,t,d0+2*dl2 .. +1]  (float2)
        {
            const int dl2 = tid & 15, tc = tid >> 4;   // 16 chunks of 32 t
            if (dl2 < nd2) {
                const float2* ep = (const float2*)(enc + (size_t)(b * ENC_T + (tc << 5)) * NDIM + d0) + dl2;
                const float* sp = spad + PADZ + (tc << 5);
                float ax0=0.f, ay0=0.f, ax1=0.f, ay1=0.f;
#pragma unroll 8
                for (int j = 0; j < 32; j += 2) {
                    float2 ev0 = ep[(size_t)(j)     * (NDIM/2)];
                    float2 ev1 = ep[(size_t)(j + 1) * (NDIM/2)];
                    float s0 = sp[j], s1 = sp[j + 1];
                    ax0 = fmaf(s0, ev0.x, ax0);
                    ay0 = fmaf(s0, ev0.y, ay0);
                    ax1 = fmaf(s1, ev1.x, ax1);
                    ay1 = fmaf(s1, ev1.y, ay1);
                }
                red2[(tc << 4) + dl2] = make_float2(ax0 + ax1, ay0 + ay1);
            }
        }
        __syncthreads();
        const int rowo = (b << 10) + s;
        if (tid < nd2) {
            float2 c = red2[tid];
#pragma unroll
            for (int g = 1; g < 16; ++g) {
                float2 v = red2[(g << 4) + tid];
                c.x += v.x; c.y += v.y;
            }
            const int d = d0 + (tid << 1);
            float2 outv = (s < ol) ? c : make_float2(0.0f, 0.0f);
            *(float2*)(att_out + (size_t)rowo * NDIM + d) = outv;
            float2 mm2 = make_float2(0.0f, 0.0f);
            if (s + 1 < ol)
                mm2 = (s + 1 < DEC_T) ? *(const float2*)(mel + (size_t)(rowo + 1) * NDIM + d)
                                      : make_float2(0.0f, 0.0f);
            *(float2*)(q_s + (tid << 1)) =
                make_float2((c.x + mm2.x) * ALPHA, (c.y + mm2.y) * ALPHA);
        }
        if (sub == 0) {
            att_sc[(size_t)rowo * ENC_T + tid]       = sc0;
            att_sc[(size_t)rowo * ENC_T + tid + 256] = sc1;
        }
        __syncthreads();
    }
}

extern "C" void kernel_launch(void* const* d_in, const int* in_sizes, int n_in,
                              void* d_out, int out_size) {
    const float* enc     = (const float*)d_in[0];
    const float* mel     = (const float*)d_in[1];
    const int*   out_len = (const int*)  d_in[3];
    const float* wlin    = (const float*)d_in[4];
    const float* wconv   = (const float*)d_in[5];
    float* att_out = (float*)d_out;
    float* att_sc  = att_out + (size_t)NB * DEC_T * NDIM;

    cudaFuncSetAttribute(attn_persist,
                         cudaFuncAttributeMaxDynamicSharedMemorySize, SM_BYTES);

    attn_init<<<1, 32>>>();
    attn_persist<<<NCTAS, NTHR, SM_BYTES>>>(enc, mel, out_len, wlin, wconv,
                                            att_out, att_sc);
}

// round 12
// speedup vs baseline: 1.0255x; 1.0255x over previous
#include <cuda_runtime.h>
#include <cuda_bf16.h>

#define NB     16
#define ENC_T  512
#define DEC_T  1024
#define NDIM   512
#define NSUB   18
#define NCTAS  (NB * NSUB)   // 288
#define NTHR   256
#define PADZ   16
#define PADTOT 544
#define ALPHA  2.885390082f  // 2*log2(e)

typedef unsigned long long u64;

// smem layout (bytes per CTA), 16B-aligned (max nd = 30)
#define OFF_W    0            // 30*32*16 = 15360
#define OFF_CC   15360        // 30*512*4 = 61440
#define OFF_RED  76800        // 4*512*4  = 8192 (aliased by float2 GEMV partials)
#define OFF_SPAD 84992        // 544*4    = 2176 (holds UNNORMALIZED exp)
#define OFF_Q    87168        // 128
#define OFF_WL   87296        // 128
#define OFF_WRED 87424        // 64
#define SM_BYTES 87488

__device__ __forceinline__ u64 pack2(float x, float y) {
    u64 r;
    asm("mov.b64 %0, {%1, %2};" : "=l"(r)
        : "r"(__float_as_uint(x)), "r"(__float_as_uint(y)));
    return r;
}
__device__ __forceinline__ void unpack2(u64 v, float& x, float& y) {
    unsigned a, b;
    asm("mov.b64 {%0, %1}, %2;" : "=r"(a), "=r"(b) : "l"(v));
    x = __uint_as_float(a); y = __uint_as_float(b);
}
__device__ __forceinline__ u64 ffma2(u64 a, u64 b, u64 c) {
    u64 d;
    asm("fma.rn.f32x2 %0, %1, %2, %3;" : "=l"(d) : "l"(a), "l"(b), "l"(c));
    return d;
}
__device__ __forceinline__ float hsum2(u64 v) {
    float x, y; unpack2(v, x, y); return x + y;
}
// input X already ALPHA-scaled: tanh = 1 - 2/(ex2(X)+1)
__device__ __forceinline__ float tanh_pre(float X) {
    float e;
    asm("ex2.approx.f32 %0, %1;" : "=f"(e) : "f"(X));
    float r;
    asm("rcp.approx.f32 %0, %1;" : "=f"(r) : "f"(e + 1.0f));
    return fmaf(-2.0f, r, 1.0f);
}

// ---------- persistent globals ----------
__device__ float    g_lpart[2][NB][NSUB][ENC_T];   // [sub][t]: coalesced R/W
__device__ unsigned g_bar[NB][32];                 // 128B per batch (no false sharing)

__global__ void attn_init() {
    if (threadIdx.x < NB) g_bar[threadIdx.x][0] = 0;
}

__global__ void __launch_bounds__(NTHR, 2)
attn_persist(const float* __restrict__ enc,
             const float* __restrict__ mel,
             const int*   __restrict__ out_len,
             const float* __restrict__ w_lin,
             const float* __restrict__ w_conv,
             float* __restrict__ att_out,
             float* __restrict__ att_sc) {
    extern __shared__ char smraw[];
    ulonglong2* w2   = (ulonglong2*)(smraw + OFF_W);
    float*      cc_s = (float*)(smraw + OFF_CC);
    float*      red  = (float*)(smraw + OFF_RED);
    float2*     red2 = (float2*)(smraw + OFF_RED);
    float*      spad = (float*)(smraw + OFF_SPAD);
    float*      q_s  = (float*)(smraw + OFF_Q);
    float*      wl_s = (float*)(smraw + OFF_WL);
    float*      wred = (float*)(smraw + OFF_WRED);

    const int tid  = threadIdx.x;
    const int b    = blockIdx.x & 15;     // batch (adjacent bids -> different batches)
    const int sub  = blockIdx.x >> 4;     // 0..17 d-slice
    const int nd   = (sub < 4) ? 30 : 28;                           // even sizes
    const int d0   = (sub < 4) ? 30 * sub : 120 + 28 * (sub - 4);   // even d0
    const int nd2  = nd >> 1;
    const int warp = tid >> 5, lane = tid & 31;
    const int dg   = warp >> 1;                       // 0..3 d-group
    const int tslot = ((warp & 1) << 5) | lane;       // 0..63
    const int t0   = tslot << 3;                      // 8 t per thread
    const int ol   = out_len[b];

    // weights (pre-scaled by ALPHA): per local d, 16 pairs for w0 then 16 for w1
    for (int e = tid; e < nd * 32; e += NTHR) {
        int d = e >> 5, j = e & 31, i = j & 15;
        const float* wb = w_conv + (size_t)(d0 + d) * 62 + ((j < 16) ? 0 : 31);
        float wm1 = (i > 0)  ? wb[2*i - 1] * ALPHA : 0.0f;
        float w0v = wb[2*i] * ALPHA;
        float wp1 = (i < 15) ? wb[2*i + 1] * ALPHA : 0.0f;
        ulonglong2 v;
        v.x = pack2(wm1, w0v);
        v.y = pack2(w0v, wp1);
        w2[(d << 5) + j] = v;
    }
    if (tid < nd) {
        wl_s[tid] = w_lin[d0 + tid];
        q_s[tid]  = (0 < ol) ? mel[(size_t)(b * DEC_T) * NDIM + d0 + tid] * ALPHA : 0.0f;
    }
    for (int i = tid; i < PADTOT; i += NTHR) spad[i] = 0.0f;
    for (int i = tid; i < nd * 512; i += NTHR) cc_s[i] = 0.0f;
    __syncthreads();

    unsigned bar_target = 0;
    float inv_prev = 1.0f;   // 1/sum(exp) of previous step (spad holds raw exp)

    for (int s = 0; s < DEC_T; ++s) {
        const int par = s & 1;

        // ===== phase A: conv0(exp) + incremental conv1, scaled by inv_prev =====
        u64 Ws[20];
        {
            const float4* sp4 = reinterpret_cast<const float4*>(spad + t0);
#pragma unroll
            for (int j = 0; j < 10; ++j) {
                float4 f = sp4[j];
                Ws[2*j]   = pack2(f.x, f.y);
                Ws[2*j+1] = pack2(f.z, f.w);
            }
        }

        float lacc0=0.f,lacc1=0.f,lacc2=0.f,lacc3=0.f;
        float lacc4=0.f,lacc5=0.f,lacc6=0.f,lacc7=0.f;
        const float invp = inv_prev;

#pragma unroll 1
        for (int d = dg; d < nd; d += 4) {
            float* ccp = cc_s + (d << 9) + t0;
            float4 cc0 = reinterpret_cast<float4*>(ccp)[0];
            float4 cc1 = reinterpret_cast<float4*>(ccp)[1];
            const ulonglong2* wr = w2 + (d << 5);

            u64 as0=0,as1=0,as2=0,as3=0,as4=0,as5=0,as6=0,as7=0;
            u64 av0=0,av1=0,av2=0,av3=0,av4=0,av5=0,av6=0,av7=0;
#pragma unroll
            for (int i = 0; i < 16; ++i) {
                ulonglong2 A  = wr[i];
                ulonglong2 Bv = wr[16 + i];
                as0 = ffma2(A.x,  Ws[i],     as0);
                as1 = ffma2(A.y,  Ws[i + 1], as1);
                as2 = ffma2(A.x,  Ws[i + 1], as2);
                as3 = ffma2(A.y,  Ws[i + 2], as3);
                as4 = ffma2(A.x,  Ws[i + 2], as4);
                as5 = ffma2(A.y,  Ws[i + 3], as5);
                as6 = ffma2(A.x,  Ws[i + 3], as6);
                as7 = ffma2(A.y,  Ws[i + 4], as7);
                av0 = ffma2(Bv.x, Ws[i],     av0);
                av1 = ffma2(Bv.y, Ws[i + 1], av1);
                av2 = ffma2(Bv.x, Ws[i + 1], av2);
                av3 = ffma2(Bv.y, Ws[i + 2], av3);
                av4 = ffma2(Bv.x, Ws[i + 2], av4);
                av5 = ffma2(Bv.y, Ws[i + 3], av5);
                av6 = ffma2(Bv.x, Ws[i + 3], av6);
                av7 = ffma2(Bv.y, Ws[i + 4], av7);
            }
            const float qd = q_s[d], wld = wl_s[d];

            // c = cc + inv_prev * alpha*conv1(exp)   (fma, no extra op)
            float c0 = fmaf(invp, hsum2(av0), cc0.x);
            float c1 = fmaf(invp, hsum2(av1), cc0.y);
            float c2 = fmaf(invp, hsum2(av2), cc0.z);
            float c3 = fmaf(invp, hsum2(av3), cc0.w);
            float c4 = fmaf(invp, hsum2(av4), cc1.x);
            float c5 = fmaf(invp, hsum2(av5), cc1.y);
            float c6 = fmaf(invp, hsum2(av6), cc1.z);
            float c7 = fmaf(invp, hsum2(av7), cc1.w);
            reinterpret_cast<float4*>(ccp)[0] = make_float4(c0, c1, c2, c3);
            reinterpret_cast<float4*>(ccp)[1] = make_float4(c4, c5, c6, c7);

            lacc0 = fmaf(wld, tanh_pre(fmaf(invp, hsum2(as0), qd + c0)), lacc0);
            lacc1 = fmaf(wld, tanh_pre(fmaf(invp, hsum2(as1), qd + c1)), lacc1);
            lacc2 = fmaf(wld, tanh_pre(fmaf(invp, hsum2(as2), qd + c2)), lacc2);
            lacc3 = fmaf(wld, tanh_pre(fmaf(invp, hsum2(as3), qd + c3)), lacc3);
            lacc4 = fmaf(wld, tanh_pre(fmaf(invp, hsum2(as4), qd + c4)), lacc4);
            lacc5 = fmaf(wld, tanh_pre(fmaf(invp, hsum2(as5), qd + c5)), lacc5);
            lacc6 = fmaf(wld, tanh_pre(fmaf(invp, hsum2(as6), qd + c6)), lacc6);
            lacc7 = fmaf(wld, tanh_pre(fmaf(invp, hsum2(as7), qd + c7)), lacc7);
        }
        {
            float* rp = red + (dg << 9) + t0;
            reinterpret_cast<float4*>(rp)[0] = make_float4(lacc0, lacc1, lacc2, lacc3);
            reinterpret_cast<float4*>(rp)[1] = make_float4(lacc4, lacc5, lacc6, lacc7);
        }
        __syncthreads();
#pragma unroll
        for (int k = 0; k < 2; ++k) {
            const int t = tid + (k << 8);
            float lp = red[t] + red[512 + t] + red[1024 + t] + red[1536 + t];
            __stcg(&g_lpart[par][b][sub][t], lp);
        }

        // ===== per-batch barrier (release arrive, acquire poll) =====
        __syncthreads();
        if (tid == 0) {
            bar_target += (unsigned)NSUB;
            asm volatile("red.release.gpu.global.add.u32 [%0], %1;"
                         :: "l"(&g_bar[b][0]), "r"(1u) : "memory");
            unsigned cur;
            for (;;) {
                asm volatile("ld.acquire.gpu.u32 %0, [%1];"
                             : "=r"(cur) : "l"(&g_bar[b][0]));
                if ((int)(cur - bar_target) >= 0) break;
                __nanosleep(32);
            }
        }
        __syncthreads();

        // ===== phase B: exp (unnormalized), hidden reduction, GEMV, tail =====
        float lv0 = 0.0f, lv1 = 0.0f;
#pragma unroll
        for (int j = 0; j < NSUB; ++j) {
            lv0 += __ldcg(&g_lpart[par][b][j][tid]);
            lv1 += __ldcg(&g_lpart[par][b][j][tid + 256]);
        }
        const float e0 = __expf(lv0);
        const float e1 = __expf(lv1);
        spad[PADZ + tid]       = e0;
        spad[PADZ + tid + 256] = e1;
        float ssum = e0 + e1;
#pragma unroll
        for (int o = 16; o; o >>= 1) ssum += __shfl_xor_sync(0xffffffffu, ssum, o);
        if (lane == 0) wred[warp] = ssum;
        __syncthreads();

        // every thread derives inv redundantly (identical value), GEMV overlaps
        const float inv = __fdividef(1.0f,
            ((wred[0] + wred[1]) + (wred[2] + wred[3])) +
            ((wred[4] + wred[5]) + (wred[6] + wred[7])));
        inv_prev = inv;

        // ctx_unnorm[b, d-slice] = sum_t exp[t] * enc[b,t,d0+2*dl2 .. +1]
        {
            const int dl2 = tid & 15, tc = tid >> 4;   // 16 chunks of 32 t
            if (dl2 < nd2) {
                const float2* ep = (const float2*)(enc + (size_t)(b * ENC_T + (tc << 5)) * NDIM + d0) + dl2;
                const float* sp = spad + PADZ + (tc << 5);
                float ax0=0.f, ay0=0.f, ax1=0.f, ay1=0.f;
#pragma unroll 8
                for (int j = 0; j < 32; j += 2) {
                    float2 ev0 = ep[(size_t)(j)     * (NDIM/2)];
                    float2 ev1 = ep[(size_t)(j + 1) * (NDIM/2)];
                    float s0 = sp[j], s1 = sp[j + 1];
                    ax0 = fmaf(s0, ev0.x, ax0);
                    ay0 = fmaf(s0, ev0.y, ay0);
                    ax1 = fmaf(s1, ev1.x, ax1);
                    ay1 = fmaf(s1, ev1.y, ay1);
                }
                red2[(tc << 4) + dl2] = make_float2(ax0 + ax1, ay0 + ay1);
            }
        }
        const int rowo = (b << 10) + s;
        if (sub == 0) {   // normalized scores out (overlaps GEMV loads)
            att_sc[(size_t)rowo * ENC_T + tid]       = e0 * inv;
            att_sc[(size_t)rowo * ENC_T + tid + 256] = e1 * inv;
        }
        __syncthreads();
        if (tid < nd2) {
            float2 c = red2[tid];
#pragma unroll
            for (int g = 1; g < 16; ++g) {
                float2 v = red2[(g << 4) + tid];
                c.x += v.x; c.y += v.y;
            }
            c.x *= inv; c.y *= inv;       // normalize once
            const int d = d0 + (tid << 1);
            float2 outv = (s < ol) ? c : make_float2(0.0f, 0.0f);
            *(float2*)(att_out + (size_t)rowo * NDIM + d) = outv;
            float2 mm2 = make_float2(0.0f, 0.0f);
            if (s + 1 < ol)
                mm2 = (s + 1 < DEC_T) ? *(const float2*)(mel + (size_t)(rowo + 1) * NDIM + d)
                                      : make_float2(0.0f, 0.0f);
            *(float2*)(q_s + (tid << 1)) =
                make_float2((c.x + mm2.x) * ALPHA, (c.y + mm2.y) * ALPHA);
        }
        __syncthreads();
    }
}

extern "C" void kernel_launch(void* const* d_in, const int* in_sizes, int n_in,
                              void* d_out, int out_size) {
    const float* enc     = (const float*)d_in[0];
    const float* mel     = (const float*)d_in[1];
    const int*   out_len = (const int*)  d_in[3];
    const float* wlin    = (const float*)d_in[4];
    const float* wconv   = (const float*)d_in[5];
    float* att_out = (float*)d_out;
    float* att_sc  = att_out + (size_t)NB * DEC_T * NDIM;

    cudaFuncSetAttribute(attn_persist,
                         cudaFuncAttributeMaxDynamicSharedMemorySize, SM_BYTES);

    attn_init<<<1, 32>>>();
    attn_persist<<<NCTAS, NTHR, SM_BYTES>>>(enc, mel, out_len, wlin, wconv,
                                            att_out, att_sc);
}

// round 13
// speedup vs baseline: 1.1319x; 1.1037x over previous
#include <cuda_runtime.h>
#include <cuda_bf16.h>

#define NB     16
#define ENC_T  512
#define DEC_T  1024
#define NDIM   512
#define NSUB   18
#define NCTAS  (NB * NSUB)   // 288
#define NTHR   256
#define PADZ   16
#define PADTOT 544

typedef unsigned long long u64;

// smem layout (bytes per CTA), 16B-aligned (max nd = 30)
#define OFF_W    0            // 30*32*16 = 15360
#define OFF_CC   15360        // 30*512*4 = 61440
#define OFF_RED  76800        // 4*512*4  = 8192 (aliased by float2 GEMV partials)
#define OFF_SPAD 84992        // 544*4    = 2176 (holds UNNORMALIZED exp)
#define OFF_Q    87168        // 128
#define OFF_WL   87296        // 128
#define OFF_WRED 87424        // 64
#define SM_BYTES 87488

__device__ __forceinline__ u64 pack2(float x, float y) {
    u64 r;
    asm("mov.b64 %0, {%1, %2};" : "=l"(r)
        : "r"(__float_as_uint(x)), "r"(__float_as_uint(y)));
    return r;
}
__device__ __forceinline__ void unpack2(u64 v, float& x, float& y) {
    unsigned a, b;
    asm("mov.b64 {%0, %1}, %2;" : "=r"(a), "=r"(b) : "l"(v));
    x = __uint_as_float(a); y = __uint_as_float(b);
}
__device__ __forceinline__ u64 ffma2(u64 a, u64 b, u64 c) {
    u64 d;
    asm("fma.rn.f32x2 %0, %1, %2, %3;" : "=l"(d) : "l"(a), "l"(b), "l"(c));
    return d;
}
__device__ __forceinline__ float hsum2(u64 v) {
    float x, y; unpack2(v, x, y); return x + y;
}
// HW tanh: single MUFU op (sm_75+)
__device__ __forceinline__ float tanh_hw(float x) {
    float r;
    asm("tanh.approx.f32 %0, %1;" : "=f"(r) : "f"(x));
    return r;
}

// ---------- persistent globals ----------
__device__ float    g_lpart[2][NB][NSUB][ENC_T];   // [sub][t]: coalesced R/W
__device__ unsigned g_bar[NB][32];                 // 128B per batch (no false sharing)

__global__ void attn_init() {
    if (threadIdx.x < NB) g_bar[threadIdx.x][0] = 0;
}

__global__ void __launch_bounds__(NTHR, 2)
attn_persist(const float* __restrict__ enc,
             const float* __restrict__ mel,
             const int*   __restrict__ out_len,
             const float* __restrict__ w_lin,
             const float* __restrict__ w_conv,
             float* __restrict__ att_out,
             float* __restrict__ att_sc) {
    extern __shared__ char smraw[];
    ulonglong2* w2   = (ulonglong2*)(smraw + OFF_W);
    float*      cc_s = (float*)(smraw + OFF_CC);
    float*      red  = (float*)(smraw + OFF_RED);
    float2*     red2 = (float2*)(smraw + OFF_RED);
    float*      spad = (float*)(smraw + OFF_SPAD);
    float*      q_s  = (float*)(smraw + OFF_Q);
    float*      wl_s = (float*)(smraw + OFF_WL);
    float*      wred = (float*)(smraw + OFF_WRED);

    const int tid  = threadIdx.x;
    const int b    = blockIdx.x & 15;     // batch (adjacent bids -> different batches)
    const int sub  = blockIdx.x >> 4;     // 0..17 d-slice
    const int nd   = (sub < 4) ? 30 : 28;                           // even sizes
    const int d0   = (sub < 4) ? 30 * sub : 120 + 28 * (sub - 4);   // even d0
    const int nd2  = nd >> 1;
    const int warp = tid >> 5, lane = tid & 31;
    const int dg   = warp >> 1;                       // 0..3 d-group
    const int tslot = ((warp & 1) << 5) | lane;       // 0..63
    const int t0   = tslot << 3;                      // 8 t per thread
    const int ol   = out_len[b];

    // weights: per local d, 16 pairs for w0 then 16 for w1 (zero-padded edges)
    for (int e = tid; e < nd * 32; e += NTHR) {
        int d = e >> 5, j = e & 31, i = j & 15;
        const float* wb = w_conv + (size_t)(d0 + d) * 62 + ((j < 16) ? 0 : 31);
        float wm1 = (i > 0)  ? wb[2*i - 1] : 0.0f;
        float w0v = wb[2*i];
        float wp1 = (i < 15) ? wb[2*i + 1] : 0.0f;
        ulonglong2 v;
        v.x = pack2(wm1, w0v);
        v.y = pack2(w0v, wp1);
        w2[(d << 5) + j] = v;
    }
    if (tid < nd) {
        wl_s[tid] = w_lin[d0 + tid];
        q_s[tid]  = (0 < ol) ? mel[(size_t)(b * DEC_T) * NDIM + d0 + tid] : 0.0f;
    }
    for (int i = tid; i < PADTOT; i += NTHR) spad[i] = 0.0f;
    for (int i = tid; i < nd * 512; i += NTHR) cc_s[i] = 0.0f;
    __syncthreads();

    unsigned bar_target = 0;
    float inv_prev = 1.0f;   // 1/sum(exp) of previous step (spad holds raw exp)

    for (int s = 0; s < DEC_T; ++s) {
        const int par = s & 1;

        // ===== phase A: conv0(exp) + incremental conv1, scaled by inv_prev =====
        u64 Ws[20];
        {
            const float4* sp4 = reinterpret_cast<const float4*>(spad + t0);
#pragma unroll
            for (int j = 0; j < 10; ++j) {
                float4 f = sp4[j];
                Ws[2*j]   = pack2(f.x, f.y);
                Ws[2*j+1] = pack2(f.z, f.w);
            }
        }

        float lacc0=0.f,lacc1=0.f,lacc2=0.f,lacc3=0.f;
        float lacc4=0.f,lacc5=0.f,lacc6=0.f,lacc7=0.f;
        const float invp = inv_prev;

#pragma unroll 1
        for (int d = dg; d < nd; d += 4) {
            float* ccp = cc_s + (d << 9) + t0;
            float4 cc0 = reinterpret_cast<float4*>(ccp)[0];
            float4 cc1 = reinterpret_cast<float4*>(ccp)[1];
            const ulonglong2* wr = w2 + (d << 5);

            u64 as0=0,as1=0,as2=0,as3=0,as4=0,as5=0,as6=0,as7=0;
            u64 av0=0,av1=0,av2=0,av3=0,av4=0,av5=0,av6=0,av7=0;
#pragma unroll
            for (int i = 0; i < 16; ++i) {
                ulonglong2 A  = wr[i];
                ulonglong2 Bv = wr[16 + i];
                as0 = ffma2(A.x,  Ws[i],     as0);
                as1 = ffma2(A.y,  Ws[i + 1], as1);
                as2 = ffma2(A.x,  Ws[i + 1], as2);
                as3 = ffma2(A.y,  Ws[i + 2], as3);
                as4 = ffma2(A.x,  Ws[i + 2], as4);
                as5 = ffma2(A.y,  Ws[i + 3], as5);
                as6 = ffma2(A.x,  Ws[i + 3], as6);
                as7 = ffma2(A.y,  Ws[i + 4], as7);
                av0 = ffma2(Bv.x, Ws[i],     av0);
                av1 = ffma2(Bv.y, Ws[i + 1], av1);
                av2 = ffma2(Bv.x, Ws[i + 1], av2);
                av3 = ffma2(Bv.y, Ws[i + 2], av3);
                av4 = ffma2(Bv.x, Ws[i + 2], av4);
                av5 = ffma2(Bv.y, Ws[i + 3], av5);
                av6 = ffma2(Bv.x, Ws[i + 3], av6);
                av7 = ffma2(Bv.y, Ws[i + 4], av7);
            }
            const float qd = q_s[d], wld = wl_s[d];

            // c = cc + inv_prev * conv1(exp)
            float c0 = fmaf(invp, hsum2(av0), cc0.x);
            float c1 = fmaf(invp, hsum2(av1), cc0.y);
            float c2 = fmaf(invp, hsum2(av2), cc0.z);
            float c3 = fmaf(invp, hsum2(av3), cc0.w);
            float c4 = fmaf(invp, hsum2(av4), cc1.x);
            float c5 = fmaf(invp, hsum2(av5), cc1.y);
            float c6 = fmaf(invp, hsum2(av6), cc1.z);
            float c7 = fmaf(invp, hsum2(av7), cc1.w);
            reinterpret_cast<float4*>(ccp)[0] = make_float4(c0, c1, c2, c3);
            reinterpret_cast<float4*>(ccp)[1] = make_float4(c4, c5, c6, c7);

            lacc0 = fmaf(wld, tanh_hw(fmaf(invp, hsum2(as0), qd + c0)), lacc0);
            lacc1 = fmaf(wld, tanh_hw(fmaf(invp, hsum2(as1), qd + c1)), lacc1);
            lacc2 = fmaf(wld, tanh_hw(fmaf(invp, hsum2(as2), qd + c2)), lacc2);
            lacc3 = fmaf(wld, tanh_hw(fmaf(invp, hsum2(as3), qd + c3)), lacc3);
            lacc4 = fmaf(wld, tanh_hw(fmaf(invp, hsum2(as4), qd + c4)), lacc4);
            lacc5 = fmaf(wld, tanh_hw(fmaf(invp, hsum2(as5), qd + c5)), lacc5);
            lacc6 = fmaf(wld, tanh_hw(fmaf(invp, hsum2(as6), qd + c6)), lacc6);
            lacc7 = fmaf(wld, tanh_hw(fmaf(invp, hsum2(as7), qd + c7)), lacc7);
        }
        {
            float* rp = red + (dg << 9) + t0;
            reinterpret_cast<float4*>(rp)[0] = make_float4(lacc0, lacc1, lacc2, lacc3);
            reinterpret_cast<float4*>(rp)[1] = make_float4(lacc4, lacc5, lacc6, lacc7);
        }
        __syncthreads();
#pragma unroll
        for (int k = 0; k < 2; ++k) {
            const int t = tid + (k << 8);
            float lp = red[t] + red[512 + t] + red[1024 + t] + red[1536 + t];
            __stcg(&g_lpart[par][b][sub][t], lp);
        }

        // ===== per-batch barrier (release arrive, acquire poll) =====
        __syncthreads();
        if (tid == 0) {
            bar_target += (unsigned)NSUB;
            asm volatile("red.release.gpu.global.add.u32 [%0], %1;"
                         :: "l"(&g_bar[b][0]), "r"(1u) : "memory");
            unsigned cur;
            for (;;) {
                asm volatile("ld.acquire.gpu.u32 %0, [%1];"
                             : "=r"(cur) : "l"(&g_bar[b][0]));
                if ((int)(cur - bar_target) >= 0) break;
                __nanosleep(32);
            }
        }
        __syncthreads();

        const int rowo = (b << 10) + s;

        // prefetch next-step mel early (hides L2 latency under gather/GEMV)
        float2 mel_pf = make_float2(0.0f, 0.0f);
        if (tid < nd2 && (s + 1 < ol))   // ol <= DEC_T so s+1 < DEC_T holds
            mel_pf = *(const float2*)(mel + (size_t)(rowo + 1) * NDIM + d0 + (tid << 1));

        // ===== phase B: exp (unnormalized), hidden reduction, GEMV, tail =====
        float lv0 = 0.0f, lv1 = 0.0f;
#pragma unroll
        for (int j = 0; j < NSUB; ++j) {
            lv0 += __ldcg(&g_lpart[par][b][j][tid]);
            lv1 += __ldcg(&g_lpart[par][b][j][tid + 256]);
        }
        const float e0 = __expf(lv0);
        const float e1 = __expf(lv1);
        spad[PADZ + tid]       = e0;
        spad[PADZ + tid + 256] = e1;
        float ssum = e0 + e1;
#pragma unroll
        for (int o = 16; o; o >>= 1) ssum += __shfl_xor_sync(0xffffffffu, ssum, o);
        if (lane == 0) wred[warp] = ssum;
        __syncthreads();

        // every thread derives inv redundantly (identical value), GEMV overlaps
        const float inv = __fdividef(1.0f,
            ((wred[0] + wred[1]) + (wred[2] + wred[3])) +
            ((wred[4] + wred[5]) + (wred[6] + wred[7])));
        inv_prev = inv;

        // ctx_unnorm[b, d-slice] = sum_t exp[t] * enc[b,t,d0+2*dl2 .. +1]
        {
            const int dl2 = tid & 15, tc = tid >> 4;   // 16 chunks of 32 t
            if (dl2 < nd2) {
                const float2* ep = (const float2*)(enc + (size_t)(b * ENC_T + (tc << 5)) * NDIM + d0) + dl2;
                const float* sp = spad + PADZ + (tc << 5);
                float ax0=0.f, ay0=0.f, ax1=0.f, ay1=0.f;
#pragma unroll 8
                for (int j = 0; j < 32; j += 2) {
                    float2 ev0 = ep[(size_t)(j)     * (NDIM/2)];
                    float2 ev1 = ep[(size_t)(j + 1) * (NDIM/2)];
                    float s0 = sp[j], s1 = sp[j + 1];
                    ax0 = fmaf(s0, ev0.x, ax0);
                    ay0 = fmaf(s0, ev0.y, ay0);
                    ax1 = fmaf(s1, ev1.x, ax1);
                    ay1 = fmaf(s1, ev1.y, ay1);
                }
                red2[(tc << 4) + dl2] = make_float2(ax0 + ax1, ay0 + ay1);
            }
        }
        if (sub == 0) {   // normalized scores out (overlaps GEMV loads)
            att_sc[(size_t)rowo * ENC_T + tid]       = e0 * inv;
            att_sc[(size_t)rowo * ENC_T + tid + 256] = e1 * inv;
        }
        __syncthreads();
        if (tid < nd2) {
            float2 c = red2[tid];
#pragma unroll
            for (int g = 1; g < 16; ++g) {
                float2 v = red2[(g << 4) + tid];
                c.x += v.x; c.y += v.y;
            }
            c.x *= inv; c.y *= inv;       // normalize once
            const int d = d0 + (tid << 1);
            float2 outv = (s < ol) ? c : make_float2(0.0f, 0.0f);
            *(float2*)(att_out + (size_t)rowo * NDIM + d) = outv;
            *(float2*)(q_s + (tid << 1)) =
                make_float2(c.x + mel_pf.x, c.y + mel_pf.y);
        }
        __syncthreads();
    }
}

extern "C" void kernel_launch(void* const* d_in, const int* in_sizes, int n_in,
                              void* d_out, int out_size) {
    const float* enc     = (const float*)d_in[0];
    const float* mel     = (const float*)d_in[1];
    const int*   out_len = (const int*)  d_in[3];
    const float* wlin    = (const float*)d_in[4];
    const float* wconv   = (const float*)d_in[5];
    float* att_out = (float*)d_out;
    float* att_sc  = att_out + (size_t)NB * DEC_T * NDIM;

    cudaFuncSetAttribute(attn_persist,
                         cudaFuncAttributeMaxDynamicSharedMemorySize, SM_BYTES);

    attn_init<<<1, 32>>>();
    attn_persist<<<NCTAS, NTHR, SM_BYTES>>>(enc, mel, out_len, wlin, wconv,
                                            att_out, att_sc);
}